// round 5
// baseline (speedup 1.0000x reference)
#include <cuda_runtime.h>

#define H 480
#define W 640
#define P 256
#define GROUPS_PER_ROW (W / 4)          // 160
#define GROUPS_PER_PAIR (H * GROUPS_PER_ROW)  // 76800

// Scratch for box average (allocation-free per harness rules)
__device__ __align__(16) float g_tmp[H * W];
__device__ __align__(16) float g_box[H * W];

// ---------------------------------------------------------------------------
// Pass 1: horizontal 5-tap sum with edge clamp
// ---------------------------------------------------------------------------
__global__ void hbox_kernel(const float* __restrict__ x) {
    int idx = blockIdx.x * blockDim.x + threadIdx.x;
    if (idx >= H * W) return;
    int y = idx / W;
    int xx = idx - y * W;
    const float* row = x + y * W;
    float s = 0.0f;
#pragma unroll
    for (int d = -2; d <= 2; d++) {
        int xc = xx + d;
        xc = xc < 0 ? 0 : (xc > W - 1 ? W - 1 : xc);
        s += row[xc];
    }
    g_tmp[idx] = s;
}

// ---------------------------------------------------------------------------
// Pass 2: vertical 5-tap sum with edge clamp, divide by 25
// ---------------------------------------------------------------------------
__global__ void vbox_kernel() {
    int idx = blockIdx.x * blockDim.x + threadIdx.x;
    if (idx >= H * W) return;
    int y = idx / W;
    int xx = idx - y * W;
    float s = 0.0f;
#pragma unroll
    for (int d = -2; d <= 2; d++) {
        int yc = y + d;
        yc = yc < 0 ? 0 : (yc > H - 1 ? H - 1 : yc);
        s += g_tmp[yc * W + xx];
    }
    g_box[idx] = s / 25.0f;
}

// ---------------------------------------------------------------------------
// One bilinear translational sample for 4 consecutive x-pixels.
// Pure-translation grid => integer shift + constant fraction per (pair,sample).
// Fast path: 2 aligned float4 loads per row (window [c, c+4] always inside
// [c-r, c-r+8) since r = c&3 <= 3). Border groups use scalar clamped path.
// ---------------------------------------------------------------------------
__device__ __forceinline__ float4 sample_one(int y, int gx, float dy, float dx) {
    // vertical: per-row constants
    float py = fminf(fmaxf((float)y + dy, 0.0f), (float)(H - 1));
    float yAf = floorf(py);
    int   yA  = (int)yAf;
    float fy  = py - yAf;
    int   yB  = min(yA + 1, H - 1);
    const float* rA = g_box + yA * W;
    const float* rB = g_box + yB * W;

    float ixf = floorf(dx);
    int   ix  = (int)ixf;
    float fx  = dx - ixf;
    int   c   = gx + ix;

    float4 o;
    if (c >= 3 && c <= W - 8) {   // base >= 0 and base+8 <= W, window fully interior
        int base = c & ~3;
        int r    = c & 3;         // uniform across the block (gx % 4 == 0)
        float4 a0 = *reinterpret_cast<const float4*>(rA + base);
        float4 a1 = *reinterpret_cast<const float4*>(rA + base + 4);
        float4 b0 = *reinterpret_cast<const float4*>(rB + base);
        float4 b1 = *reinterpret_cast<const float4*>(rB + base + 4);
        // vertical lerp over the 8-float window
        float v0 = fmaf(fy, b0.x - a0.x, a0.x);
        float v1 = fmaf(fy, b0.y - a0.y, a0.y);
        float v2 = fmaf(fy, b0.z - a0.z, a0.z);
        float v3 = fmaf(fy, b0.w - a0.w, a0.w);
        float v4 = fmaf(fy, b1.x - a1.x, a1.x);
        float v5 = fmaf(fy, b1.y - a1.y, a1.y);
        float v6 = fmaf(fy, b1.z - a1.z, a1.z);
        float v7 = fmaf(fy, b1.w - a1.w, a1.w);
        float w0, w1, w2, w3, w4;
        switch (r) {
            case 0: w0 = v0; w1 = v1; w2 = v2; w3 = v3; w4 = v4; break;
            case 1: w0 = v1; w1 = v2; w2 = v3; w3 = v4; w4 = v5; break;
            case 2: w0 = v2; w1 = v3; w2 = v4; w3 = v5; w4 = v6; break;
            default: w0 = v3; w1 = v4; w2 = v5; w3 = v6; w4 = v7; break;
        }
        o.x = fmaf(fx, w1 - w0, w0);
        o.y = fmaf(fx, w2 - w1, w1);
        o.z = fmaf(fx, w3 - w2, w2);
        o.w = fmaf(fx, w4 - w3, w3);
    } else {
        // scalar border path with full clamping
        float res[4];
#pragma unroll
        for (int k = 0; k < 4; k++) {
            float pxc = fminf(fmaxf((float)(gx + k) + dx, 0.0f), (float)(W - 1));
            float x0f = floorf(pxc);
            int   x0  = (int)x0f;
            int   x1  = min(x0 + 1, W - 1);
            float wx  = pxc - x0f;
            float vA  = fmaf(wx, rA[x1] - rA[x0], rA[x0]);
            float vB  = fmaf(wx, rB[x1] - rB[x0], rB[x0]);
            res[k]    = fmaf(fy, vB - vA, vA);
        }
        o.x = res[0]; o.y = res[1]; o.z = res[2]; o.w = res[3];
    }
    return o;
}

// ---------------------------------------------------------------------------
// Main kernel: one thread -> one float4 (4 x-pixels) of one (pair,row).
// ---------------------------------------------------------------------------
__global__ void __launch_bounds__(256) descriptor_kernel(
    const float* __restrict__ offs, float* __restrict__ out)
{
    int p = blockIdx.y;
    int g = blockIdx.x * blockDim.x + threadIdx.x;   // 0 .. GROUPS_PER_PAIR-1
    int y  = g / GROUPS_PER_ROW;
    int gx = (g - y * GROUPS_PER_ROW) * 4;

    const float* po = offs + p * 4;
    float dy1 = po[0], dx1 = po[1];
    float dy2 = po[2], dx2 = po[3];

    float4 s1 = sample_one(y, gx, dy1, dx1);
    float4 s2 = sample_one(y, gx, dy2, dx2);

    float4 r;
    r.x = s1.x - s2.x;
    r.y = s1.y - s2.y;
    r.z = s1.z - s2.z;
    r.w = s1.w - s2.w;

    *reinterpret_cast<float4*>(out + ((size_t)p * H + y) * W + gx) = r;
}

extern "C" void kernel_launch(void* const* d_in, const int* in_sizes, int n_in,
                              void* d_out, int out_size) {
    const float* x    = (const float*)d_in[0];   // [1,1,480,640]
    const float* offs = (const float*)d_in[1];   // [256,2,2]
    float* out = (float*)d_out;                  // [1,256,480,640]

    const int npx = H * W;
    hbox_kernel<<<(npx + 255) / 256, 256>>>(x);
    vbox_kernel<<<(npx + 255) / 256, 256>>>();

    dim3 grid(GROUPS_PER_PAIR / 256, P, 1);      // 300 x 256 blocks
    descriptor_kernel<<<grid, 256>>>(offs, out);
}